// round 15
// baseline (speedup 1.0000x reference)
#include <cuda_runtime.h>
#include <math.h>

#define BATCH 256
#define TSTEPS 50
#define INSZ 400
#define G4 1024
#define GAMMA 0.95f
#define EPSF 1e-8f

// ---------- device scratch ----------
__device__ float g_xw[TSTEPS * BATCH * G4];
__device__ float g_h[BATCH * 256];
__device__ float g_c[BATCH * 256];
__device__ float g_r[BATCH * 256];
__device__ float g_M[BATCH * 256 * 64];
__device__ float g_wr[BATCH * 4 * 256];
__device__ float g_wu[BATCH * 256];

__device__ __forceinline__ float sigf(float x) { return 1.0f / (1.0f + expf(-x)); }

__device__ __forceinline__ unsigned tf32cvt(float f) {
    unsigned u;
    asm("cvt.rna.tf32.f32 %0, %1;" : "=r"(u) : "f"(f));
    return u;
}
__device__ __forceinline__ void mma_tf32(
    float& d0, float& d1, float& d2, float& d3,
    unsigned a0, unsigned a1, unsigned a2, unsigned a3,
    unsigned b0, unsigned b1)
{
    asm("mma.sync.aligned.m16n8k8.row.col.f32.tf32.tf32.f32 "
        "{%0,%1,%2,%3}, {%4,%5,%6,%7}, {%8,%9}, {%0,%1,%2,%3};"
        : "+f"(d0), "+f"(d1), "+f"(d2), "+f"(d3)
        : "r"(a0), "r"(a1), "r"(a2), "r"(a3), "r"(b0), "r"(b1));
}

// ---------- init ----------
__global__ void k_init() {
    int i = blockIdx.x * blockDim.x + threadIdx.x;
    if (i < BATCH * 256 * 64) g_M[i] = 1e-6f;
    if (i < BATCH * 1024) g_wr[i] = 1.0f / 256.0f;
    if (i < BATCH * 256) {
        g_h[i] = 0.0f; g_c[i] = 0.0f; g_r[i] = 0.0f;
        g_wu[i] = 1.0f / 256.0f;
    }
}

// ---------- K1: tf32 tensor-core GEMM (R13 version) ----------
__global__ __launch_bounds__(256) void k1_xw_tc(
    const float* __restrict__ X, const int* __restrict__ tgt,
    const float* __restrict__ Wih, const float* __restrict__ bl)
{
    __shared__ unsigned As[2][128][20];
    __shared__ unsigned Bs[2][16][136];
    __shared__ float bls[128];

    const int tid = threadIdx.x;
    const int lane = tid & 31, warp = tid >> 5;
    const int wm = warp & 3, wn = warp >> 2;
    const int g = lane >> 2, tg = lane & 3;
    const int m0 = blockIdx.y * 128, n0 = blockIdx.x * 128;

    if (tid < 128) bls[tid] = bl[n0 + tid];

    const int e0 = tid, e1 = tid + 256;
    const int arw0 = e0 >> 2, acq0 = e0 & 3;
    const int arw1 = e1 >> 2, acq1 = e1 & 3;
    const int bk0 = e0 >> 5, bnq0 = e0 & 31;
    const int bk1 = e1 >> 5, bnq1 = e1 & 31;

    float4 ax0, ax1, bx0, bx1;
    ax0 = *(const float4*)(X + (size_t)(m0 + arw0) * INSZ + acq0 * 4);
    ax1 = *(const float4*)(X + (size_t)(m0 + arw1) * INSZ + acq1 * 4);
    bx0 = *(const float4*)(Wih + (size_t)bk0 * G4 + n0 + bnq0 * 4);
    bx1 = *(const float4*)(Wih + (size_t)bk1 * G4 + n0 + bnq1 * 4);
    {
        uint4 u;
        u.x = tf32cvt(ax0.x); u.y = tf32cvt(ax0.y); u.z = tf32cvt(ax0.z); u.w = tf32cvt(ax0.w);
        *(uint4*)&As[0][arw0][acq0 * 4] = u;
        u.x = tf32cvt(ax1.x); u.y = tf32cvt(ax1.y); u.z = tf32cvt(ax1.z); u.w = tf32cvt(ax1.w);
        *(uint4*)&As[0][arw1][acq1 * 4] = u;
        u.x = tf32cvt(bx0.x); u.y = tf32cvt(bx0.y); u.z = tf32cvt(bx0.z); u.w = tf32cvt(bx0.w);
        *(uint4*)&Bs[0][bk0][bnq0 * 4] = u;
        u.x = tf32cvt(bx1.x); u.y = tf32cvt(bx1.y); u.z = tf32cvt(bx1.z); u.w = tf32cvt(bx1.w);
        *(uint4*)&Bs[0][bk1][bnq1 * 4] = u;
    }
    __syncthreads();

    float d[2][8][4];
#pragma unroll
    for (int i = 0; i < 2; i++)
#pragma unroll
        for (int j = 0; j < 8; j++)
#pragma unroll
            for (int q = 0; q < 4; q++) d[i][j][q] = 0.0f;

    for (int kt = 0; kt < 25; kt++) {
        const int cur = kt & 1;
        if (kt < 24) {
            const int kb = (kt + 1) * 16;
            ax0 = *(const float4*)(X + (size_t)(m0 + arw0) * INSZ + kb + acq0 * 4);
            ax1 = *(const float4*)(X + (size_t)(m0 + arw1) * INSZ + kb + acq1 * 4);
            bx0 = *(const float4*)(Wih + (size_t)(kb + bk0) * G4 + n0 + bnq0 * 4);
            bx1 = *(const float4*)(Wih + (size_t)(kb + bk1) * G4 + n0 + bnq1 * 4);
        }
#pragma unroll
        for (int ks = 0; ks < 2; ks++) {
            const int kk = ks * 8;
            unsigned af[2][4];
#pragma unroll
            for (int mt = 0; mt < 2; mt++) {
                const int r = wm * 32 + mt * 16 + g;
                af[mt][0] = As[cur][r][kk + tg];
                af[mt][1] = As[cur][r + 8][kk + tg];
                af[mt][2] = As[cur][r][kk + tg + 4];
                af[mt][3] = As[cur][r + 8][kk + tg + 4];
            }
#pragma unroll
            for (int nt = 0; nt < 8; nt++) {
                const int c = wn * 64 + nt * 8 + g;
                unsigned b0 = Bs[cur][kk + tg][c];
                unsigned b1 = Bs[cur][kk + tg + 4][c];
                mma_tf32(d[0][nt][0], d[0][nt][1], d[0][nt][2], d[0][nt][3],
                         af[0][0], af[0][1], af[0][2], af[0][3], b0, b1);
                mma_tf32(d[1][nt][0], d[1][nt][1], d[1][nt][2], d[1][nt][3],
                         af[1][0], af[1][1], af[1][2], af[1][3], b0, b1);
            }
        }
        if (kt < 24) {
            const int nxt = 1 - cur;
            uint4 u;
            u.x = tf32cvt(ax0.x); u.y = tf32cvt(ax0.y); u.z = tf32cvt(ax0.z); u.w = tf32cvt(ax0.w);
            *(uint4*)&As[nxt][arw0][acq0 * 4] = u;
            u.x = tf32cvt(ax1.x); u.y = tf32cvt(ax1.y); u.z = tf32cvt(ax1.z); u.w = tf32cvt(ax1.w);
            *(uint4*)&As[nxt][arw1][acq1 * 4] = u;
            u.x = tf32cvt(bx0.x); u.y = tf32cvt(bx0.y); u.z = tf32cvt(bx0.z); u.w = tf32cvt(bx0.w);
            *(uint4*)&Bs[nxt][bk0][bnq0 * 4] = u;
            u.x = tf32cvt(bx1.x); u.y = tf32cvt(bx1.y); u.z = tf32cvt(bx1.z); u.w = tf32cvt(bx1.w);
            *(uint4*)&Bs[nxt][bk1][bnq1 * 4] = u;
            __syncthreads();
        }
    }

#pragma unroll
    for (int mt = 0; mt < 2; mt++) {
#pragma unroll
        for (int rp = 0; rp < 2; rp++) {
            const int m = m0 + wm * 32 + mt * 16 + g + rp * 8;
            const int bb = m / TSTEPS, t = m % TSTEPS;
            const float* offrow = (t > 0) ? (Wih + (size_t)(400 + tgt[m - 1]) * G4) : (const float*)0;
            float* dst = g_xw + ((size_t)t * BATCH + bb) * G4 + n0;
#pragma unroll
            for (int nt = 0; nt < 8; nt++) {
                const int c = wn * 64 + nt * 8 + tg * 2;
                float v0 = d[mt][nt][rp * 2 + 0] + bls[c];
                float v1 = d[mt][nt][rp * 2 + 1] + bls[c + 1];
                if (offrow) { v0 += offrow[n0 + c]; v1 += offrow[n0 + c + 1]; }
                float2 v = make_float2(v0, v1);
                *(float2*)(dst + c) = v;
            }
        }
    }
}

// ---------- K2: recurrent GEMM + LSTM, double-buffered (R8 version) ----------
__global__ __launch_bounds__(256) void k2_step(
    const float* __restrict__ Wih, const float* __restrict__ Whh, int t)
{
    __shared__ float As2[2][16][34];
    __shared__ float Bs2[2][16][68];
    const int tid = threadIdx.x;
    const int tx = tid & 15, ty = tid >> 4;
    const int b0 = blockIdx.x * 32, u0 = blockIdx.y * 16;
    const int arow = tid >> 3, akq = tid & 7;
    const int bk = tid >> 4, bu = tid & 15;
    const float* WihR = Wih + (size_t)405 * G4;

    const int uP = u0 + tx;
    const int bP0 = b0 + ty * 2, bP1 = bP0 + 1;
    const float* xwA = g_xw + ((size_t)t * BATCH + bP0) * G4;
    const float* xwB = g_xw + ((size_t)t * BATCH + bP1) * G4;
    float xA0 = xwA[uP], xA1 = xwA[256 + uP], xA2 = xwA[512 + uP], xA3 = xwA[768 + uP];
    float xB0 = xwB[uP], xB1 = xwB[256 + uP], xB2 = xwB[512 + uP], xB3 = xwB[768 + uP];
    float cA = g_c[bP0 * 256 + uP], cB = g_c[bP1 * 256 + uP];

    {
        float2 av = *(const float2*)(g_r + (size_t)(b0 + arow) * 256 + akq * 2);
        As2[0][akq * 2][arow] = av.x; As2[0][akq * 2 + 1][arow] = av.y;
        const float* wrow = WihR + (size_t)bk * G4 + u0 + bu;
        Bs2[0][bk][bu * 4 + 0] = wrow[0];
        Bs2[0][bk][bu * 4 + 1] = wrow[256];
        Bs2[0][bk][bu * 4 + 2] = wrow[512];
        Bs2[0][bk][bu * 4 + 3] = wrow[768];
    }
    __syncthreads();

    float acc[2][4] = {};
    for (int kt = 0; kt < 32; kt++) {
        const int cur = kt & 1;
        float2 avn = make_float2(0.f, 0.f);
        float bgn0 = 0.f, bgn1 = 0.f, bgn2 = 0.f, bgn3 = 0.f;
        if (kt < 31) {
            const int kn = kt + 1;
            const float* src = (kn < 16) ? g_r : g_h;
            avn = *(const float2*)(src + (size_t)(b0 + arow) * 256 + (kn & 15) * 16 + akq * 2);
            const float* W = (kn < 16) ? WihR : Whh;
            const float* wrow = W + (size_t)((kn & 15) * 16 + bk) * G4 + u0 + bu;
            bgn0 = wrow[0]; bgn1 = wrow[256]; bgn2 = wrow[512]; bgn3 = wrow[768];
        }
#pragma unroll
        for (int k = 0; k < 16; k++) {
            float a0 = As2[cur][k][ty * 2], a1 = As2[cur][k][ty * 2 + 1];
            float4 b = *(float4*)&Bs2[cur][k][tx * 4];
            acc[0][0] += a0 * b.x; acc[0][1] += a0 * b.y; acc[0][2] += a0 * b.z; acc[0][3] += a0 * b.w;
            acc[1][0] += a1 * b.x; acc[1][1] += a1 * b.y; acc[1][2] += a1 * b.z; acc[1][3] += a1 * b.w;
        }
        if (kt < 31) {
            const int nxt = 1 - cur;
            As2[nxt][akq * 2][arow] = avn.x; As2[nxt][akq * 2 + 1][arow] = avn.y;
            Bs2[nxt][bk][bu * 4 + 0] = bgn0;
            Bs2[nxt][bk][bu * 4 + 1] = bgn1;
            Bs2[nxt][bk][bu * 4 + 2] = bgn2;
            Bs2[nxt][bk][bu * 4 + 3] = bgn3;
            __syncthreads();
        }
    }
    {
        float gi = acc[0][0] + xA0, gf = acc[0][1] + xA1, gg = acc[0][2] + xA2, go = acc[0][3] + xA3;
        float cc = sigf(gf) * cA + sigf(gi) * tanhf(gg);
        g_c[bP0 * 256 + uP] = cc;
        g_h[bP0 * 256 + uP] = sigf(go) * tanhf(cc);
    }
    {
        float gi = acc[1][0] + xB0, gf = acc[1][1] + xB1, gg = acc[1][2] + xB2, go = acc[1][3] + xB3;
        float cc = sigf(gf) * cB + sigf(gi) * tanhf(gg);
        g_c[bP1 * 256 + uP] = cc;
        g_h[bP1 * 256 + uP] = sigf(go) * tanhf(cc);
    }
}

// ---------- K4: 2 batches/CTA, short critical path, per-half named barriers ----------
// smem float offsets (sM stride 68 for aligned LDS.128 in sims)
#define Q_M     0        // [2][256*68] = 34816
#define Q_PART  34816    // [2][16][264] = 8448
#define Q_K     43264    // [2][256]
#define Q_SIM   43776    // [2][1024]
#define Q_WW    45824    // [2][1024]
#define Q_WU    47872    // [2][256]
#define Q_H     48384    // [2][256]
#define Q_RD    48896    // [2][256]
#define Q_PR    49408    // [2][512]
#define Q_WP    50432    // [2][40]
#define Q_EX    50512    // [2][16]
#define Q_LU    50544    // int [2][4]
#define K4_FLOATS 50552
#define K4_BYTES (K4_FLOATS * 4)

__global__ __launch_bounds__(1024) void k4_mem(
    const float* __restrict__ Wkp, const float* __restrict__ bkp,
    const float* __restrict__ Wout, const float* __restrict__ bout,
    float* __restrict__ out, int t)
{
    extern __shared__ float sm[];
    float* sMall   = sm + Q_M;
    float* spart   = sm + Q_PART;
    float* skall   = sm + Q_K;
    float* ssimall = sm + Q_SIM;
    float* swwall  = sm + Q_WW;
    float* swuall  = sm + Q_WU;
    float* shall   = sm + Q_H;
    float* srdall  = sm + Q_RD;
    float* spRall  = sm + Q_PR;
    float* swpall  = sm + Q_WP;
    float* sexall  = sm + Q_EX;
    int*   sluall  = (int*)(sm + Q_LU);

    const int tid = threadIdx.x;
    const int half = tid >> 9, lt = tid & 511;
    const int lane = tid & 31;
    const int widl = lt >> 5;                 // warp within half (0..15)
    const int b = blockIdx.x * 2 + half;

    float* sM     = sMall + half * 17408;
    float* sk     = skall + half * 256;
    float* ssim   = ssimall + half * 1024;
    float* sww    = swwall + half * 1024;
    float* swu    = swuall + half * 256;
    float* sh     = shall + half * 256;
    float* sreads = srdall + half * 256;
    float* spR    = spRall + half * 512;
    float* swp    = swpall + half * 40;
    float* sex    = sexall + half * 16;
    int*   slu    = sluall + half * 4;

#define HBAR() asm volatile("bar.sync %0, 512;" :: "r"(half + 1) : "memory")

    // ---- P0: per-half h/wu loads ----
    if (lt < 256) {
        swu[lt] = g_wu[b * 256 + lt];
        sh[lt]  = g_h[b * 256 + lt];
    }
    __syncthreads();

    // ---- P1 (overlap): warps 0-15 GEMV both batches | warps 16-29 M load both | warps 30/31 top-4 ----
    {
        const int warp = tid >> 5;
        if (warp < 16) {
            const int kbase = warp * 16;
            float h0[16], h1[16];
#pragma unroll
            for (int kk = 0; kk < 16; kk++) {
                h0[kk] = shall[kbase + kk];
                h1[kk] = shall[256 + kbase + kk];
            }
#pragma unroll
            for (int g = 0; g < 9; g++) {
                int col = g * 32 + lane;
                if (col < 260) {
                    const float* wp = Wkp + (size_t)kbase * 260 + col;
                    float p0 = 0.0f, p1 = 0.0f;
#pragma unroll
                    for (int kk = 0; kk < 16; kk++) {
                        float wv = wp[(size_t)kk * 260];
                        p0 += h0[kk] * wv;
                        p1 += h1[kk] * wv;
                    }
                    spart[warp * 264 + col] = p0;
                    spart[4224 + warp * 264 + col] = p1;
                }
            }
        } else if (warp < 30) {
            const int tm = tid - 512;           // 0..447
            const int cta0 = blockIdx.x * 2;
            const float4* gm4 = (const float4*)(g_M + (size_t)cta0 * 16384);
#pragma unroll
            for (int e = 0; e < 19; e++) {
                int gi = e * 448 + tm;
                if (gi < 8192) {
                    int bb = gi >> 12;
                    int idx = gi & 4095;
                    float4 v = gm4[(size_t)bb * 4096 + idx];
                    int n = (idx * 4) >> 6, dd = (idx * 4) & 63;
                    float* dst = sMall + bb * 17408 + n * 68 + dd;
                    dst[0] = v.x; dst[1] = v.y; dst[2] = v.z; dst[3] = v.w;
                }
            }
        } else {
            const int hh = warp - 30;           // top-4 for half hh
            const float* wu = swuall + hh * 256;
            int* sl = sluall + hh * 4;
            float v[8];
#pragma unroll
            for (int j = 0; j < 8; j++) v[j] = wu[j * 32 + lane];
#pragma unroll
            for (int r = 0; r < 4; r++) {
                float bv = v[0]; int bi = lane;
#pragma unroll
                for (int j = 1; j < 8; j++) {
                    int idx = j * 32 + lane;
                    if (v[j] < bv) { bv = v[j]; bi = idx; }
                }
#pragma unroll
                for (int o = 16; o > 0; o >>= 1) {
                    float ov = __shfl_xor_sync(0xffffffffu, bv, o);
                    int   oi = __shfl_xor_sync(0xffffffffu, bi, o);
                    if (ov < bv || (ov == bv && oi < bi)) { bv = ov; bi = oi; }
                }
                if (lane == 0) sl[r] = bi;
#pragma unroll
                for (int j = 0; j < 8; j++)
                    if (bi == j * 32 + lane) v[j] = 3.0e38f;
            }
        }
    }
    __syncthreads();

    // ---- P2: kp partial sum + activations (per half) ----
    if (lt < 260) {
        float s = bkp[lt];
        const float* sp = spart + half * 4224;
#pragma unroll
        for (int w = 0; w < 16; w++) s += sp[w * 264 + lt];
        if (lt < 256) sk[lt] = tanhf(s);
        else sex[4 + (lt - 256)] = sigf(s);
    }
    HBAR();

    // ---- P3: w_w (lt<256) || key norms (warps 8-11) ----
    if (lt < 256) {
        float a0 = sex[4], a1 = sex[5], a2 = sex[6], a3 = sex[7];
        const float* wr = g_wr + (size_t)b * 1024;
        float4 w;
        w.x = a0 * wr[lt]       + (1.0f - a0) * ((lt == slu[0]) ? 1.0f : 0.0f);
        w.y = a1 * wr[256 + lt] + (1.0f - a1) * ((lt == slu[1]) ? 1.0f : 0.0f);
        w.z = a2 * wr[512 + lt] + (1.0f - a2) * ((lt == slu[2]) ? 1.0f : 0.0f);
        w.w = a3 * wr[768 + lt] + (1.0f - a3) * ((lt == slu[3]) ? 1.0f : 0.0f);
        *(float4*)&sww[lt * 4] = w;
    } else if (widl >= 8 && widl < 12) {
        const int w4 = widl - 8;
        float v0 = sk[w4 * 64 + lane], v1 = sk[w4 * 64 + lane + 32];
        float s = v0 * v0 + v1 * v1;
#pragma unroll
        for (int o = 16; o > 0; o >>= 1) s += __shfl_xor_sync(0xffffffffu, s, o);
        if (lane == 0) sex[w4] = 1.0f / (sqrtf(s) + EPSF);
    }
    HBAR();

    // ---- P4: erase + additive write; persist M ----
    {
        const int d = lt & 63, nb = lt >> 6;
        const int lu0 = slu[0];
        const float k0 = sk[d], k1 = sk[64 + d], k2 = sk[128 + d], k3 = sk[192 + d];
        float* gmw = g_M + (size_t)b * 16384;
#pragma unroll 4
        for (int e = 0; e < 32; e++) {
            int n = e * 8 + nb;
            float4 w = *(float4*)&sww[n * 4];
            float v = (n == lu0) ? 0.0f : sM[n * 68 + d];
            v += w.x * k0 + w.y * k1 + w.z * k2 + w.w * k3;
            sM[n * 68 + d] = v;
            gmw[n * 64 + d] = v;
        }
    }
    HBAR();

    // ---- P5: row norms + cosine sims (2 threads/row, aligned LDS.128) ----
    {
        const int row = lt >> 1, hf = lt & 1;
        const float* mrow = sM + row * 68 + hf * 32;
        const float* kb = sk + hf * 32;
        float s = 0, d0 = 0, d1 = 0, d2 = 0, d3 = 0;
#pragma unroll
        for (int dd = 0; dd < 32; dd += 4) {
            float4 mv  = *(const float4*)&mrow[dd];
            float4 kk0 = *(const float4*)&kb[dd];
            float4 kk1 = *(const float4*)&kb[64 + dd];
            float4 kk2 = *(const float4*)&kb[128 + dd];
            float4 kk3 = *(const float4*)&kb[192 + dd];
            s  += mv.x * mv.x + mv.y * mv.y + mv.z * mv.z + mv.w * mv.w;
            d0 += mv.x * kk0.x + mv.y * kk0.y + mv.z * kk0.z + mv.w * kk0.w;
            d1 += mv.x * kk1.x + mv.y * kk1.y + mv.z * kk1.z + mv.w * kk1.w;
            d2 += mv.x * kk2.x + mv.y * kk2.y + mv.z * kk2.z + mv.w * kk2.w;
            d3 += mv.x * kk3.x + mv.y * kk3.y + mv.z * kk3.z + mv.w * kk3.w;
        }
        s  += __shfl_xor_sync(0xffffffffu, s, 1);
        d0 += __shfl_xor_sync(0xffffffffu, d0, 1);
        d1 += __shfl_xor_sync(0xffffffffu, d1, 1);
        d2 += __shfl_xor_sync(0xffffffffu, d2, 1);
        d3 += __shfl_xor_sync(0xffffffffu, d3, 1);
        if (hf == 0) {
            float inv = 1.0f / (sqrtf(s) + EPSF);
            ssim[row]       = d0 * inv * sex[0];
            ssim[256 + row] = d1 * inv * sex[1];
            ssim[512 + row] = d2 * inv * sex[2];
            ssim[768 + row] = d3 * inv * sex[3];
        }
    }
    HBAR();

    // ---- P6: softmax per head, one warp per head (warp-local, no barriers) ----
    if (widl < 4) {
        float* row = ssim + widl * 256;
        float v[8];
#pragma unroll
        for (int j = 0; j < 8; j++) v[j] = row[j * 32 + lane];
        float mx = v[0];
#pragma unroll
        for (int j = 1; j < 8; j++) mx = fmaxf(mx, v[j]);
#pragma unroll
        for (int o = 16; o > 0; o >>= 1) mx = fmaxf(mx, __shfl_xor_sync(0xffffffffu, mx, o));
        float sum = 0.0f;
#pragma unroll
        for (int j = 0; j < 8; j++) { v[j] = expf(v[j] - mx); sum += v[j]; }
#pragma unroll
        for (int o = 16; o > 0; o >>= 1) sum += __shfl_xor_sync(0xffffffffu, sum, o);
        float inv = 1.0f / sum;
#pragma unroll
        for (int j = 0; j < 8; j++) row[j * 32 + lane] = v[j] * inv;
    }
    HBAR();

    // ---- P7: usage update + w_r persist (lt<256), reads partial (all) ----
    if (lt < 256) {
        float wrs = ssim[lt] + ssim[256 + lt] + ssim[512 + lt] + ssim[768 + lt];
        float4 w = *(float4*)&sww[lt * 4];
        g_wu[b * 256 + lt] = GAMMA * swu[lt] + wrs + (w.x + w.y + w.z + w.w);
        float* gwr = g_wr + (size_t)b * 1024;
        gwr[lt] = ssim[lt]; gwr[256 + lt] = ssim[256 + lt];
        gwr[512 + lt] = ssim[512 + lt]; gwr[768 + lt] = ssim[768 + lt];
    }
    {
        const int sub = lt >> 8;
        const int r = (lt >> 6) & 3, dd = lt & 63;
        const float* wr2 = ssim + r * 256 + sub * 128;
        const float* mbase = sM + sub * 128 * 68;
        float acc = 0.0f;
#pragma unroll 4
        for (int n = 0; n < 128; n += 4) {
            float4 w = *(const float4*)&wr2[n];
            acc += w.x * mbase[n * 68 + dd] + w.y * mbase[(n + 1) * 68 + dd]
                 + w.z * mbase[(n + 2) * 68 + dd] + w.w * mbase[(n + 3) * 68 + dd];
        }
        spR[lt] = acc;
    }
    HBAR();
    if (lt < 256) {
        float v = spR[lt] + spR[lt + 256];
        sreads[lt] = v;
        g_r[b * 256 + lt] = v;
    }
    HBAR();

    // ---- P8: output head ----
    if (lt < 256) {
        const float* w1 = Wout + (size_t)lt * 5;
        const float* w2 = Wout + (size_t)(256 + lt) * 5;
        float hv = sh[lt], rv = sreads[lt];
        float p0 = hv * w1[0] + rv * w2[0];
        float p1 = hv * w1[1] + rv * w2[1];
        float p2 = hv * w1[2] + rv * w2[2];
        float p3 = hv * w1[3] + rv * w2[3];
        float p4 = hv * w1[4] + rv * w2[4];
#pragma unroll
        for (int o = 16; o > 0; o >>= 1) {
            p0 += __shfl_xor_sync(0xffffffffu, p0, o);
            p1 += __shfl_xor_sync(0xffffffffu, p1, o);
            p2 += __shfl_xor_sync(0xffffffffu, p2, o);
            p3 += __shfl_xor_sync(0xffffffffu, p3, o);
            p4 += __shfl_xor_sync(0xffffffffu, p4, o);
        }
        if (lane == 0) {
            swp[widl * 5 + 0] = p0; swp[widl * 5 + 1] = p1; swp[widl * 5 + 2] = p2;
            swp[widl * 5 + 3] = p3; swp[widl * 5 + 4] = p4;
        }
    }
    HBAR();
    if (lt == 0) {
        float l[5];
#pragma unroll
        for (int c = 0; c < 5; c++) {
            float s = bout[c];
#pragma unroll
            for (int w = 0; w < 8; w++) s += swp[w * 5 + c];
            l[c] = s;
        }
        float mx = l[0];
#pragma unroll
        for (int c = 1; c < 5; c++) mx = fmaxf(mx, l[c]);
        float e[5], s = 0.0f;
#pragma unroll
        for (int c = 0; c < 5; c++) { e[c] = expf(l[c] - mx); s += e[c]; }
        float inv = 1.0f / s;
        float* o = out + ((size_t)b * TSTEPS + t) * 5;
#pragma unroll
        for (int c = 0; c < 5; c++) o[c] = e[c] * inv;
    }
#undef HBAR
}

// ---------- launch ----------
extern "C" void kernel_launch(void* const* d_in, const int* in_sizes, int n_in,
                              void* d_out, int out_size) {
    const float* X    = (const float*)d_in[0];
    const int*   tgt  = (const int*)d_in[1];
    const float* Wih  = (const float*)d_in[2];
    const float* Whh  = (const float*)d_in[3];
    const float* bl   = (const float*)d_in[4];
    const float* Wkp  = (const float*)d_in[5];
    const float* bkp  = (const float*)d_in[6];
    const float* Wout = (const float*)d_in[7];
    const float* bout = (const float*)d_in[8];
    float* out = (float*)d_out;

    cudaFuncSetAttribute(k4_mem, cudaFuncAttributeMaxDynamicSharedMemorySize, K4_BYTES);

    k_init<<<16384, 256>>>();
    k1_xw_tc<<<dim3(8, 100), 256>>>(X, tgt, Wih, bl);
    for (int t = 0; t < TSTEPS; t++) {
        k2_step<<<dim3(8, 16), 256>>>(Wih, Whh, t);
        k4_mem<<<128, 1024, K4_BYTES>>>(Wkp, bkp, Wout, bout, out, t);
    }
}

// round 16
// speedup vs baseline: 1.1086x; 1.1086x over previous
#include <cuda_runtime.h>
#include <cooperative_groups.h>
#include <math.h>

namespace cg = cooperative_groups;

#define BATCH 256
#define TSTEPS 50
#define INSZ 400
#define G4 1024
#define GAMMA 0.95f
#define EPSF 1e-8f

// ---------- device scratch ----------
__device__ float g_xw[TSTEPS * BATCH * G4];
__device__ float g_hA[BATCH * 256];
__device__ float g_hB[BATCH * 256];
__device__ float g_r[BATCH * 256];

__device__ __forceinline__ float sigf(float x) { return 1.0f / (1.0f + expf(-x)); }

__device__ __forceinline__ unsigned tf32cvt(float f) {
    unsigned u;
    asm("cvt.rna.tf32.f32 %0, %1;" : "=r"(u) : "f"(f));
    return u;
}
__device__ __forceinline__ void mma_tf32(
    float& d0, float& d1, float& d2, float& d3,
    unsigned a0, unsigned a1, unsigned a2, unsigned a3,
    unsigned b0, unsigned b1)
{
    asm("mma.sync.aligned.m16n8k8.row.col.f32.tf32.tf32.f32 "
        "{%0,%1,%2,%3}, {%4,%5,%6,%7}, {%8,%9}, {%0,%1,%2,%3};"
        : "+f"(d0), "+f"(d1), "+f"(d2), "+f"(d3)
        : "r"(a0), "r"(a1), "r"(a2), "r"(a3), "r"(b0), "r"(b1));
}

// ---------- K1: tf32 tensor-core GEMM (R13 version, unchanged) ----------
__global__ __launch_bounds__(256) void k1_xw_tc(
    const float* __restrict__ X, const int* __restrict__ tgt,
    const float* __restrict__ Wih, const float* __restrict__ bl)
{
    __shared__ unsigned As[2][128][20];
    __shared__ unsigned Bs[2][16][136];
    __shared__ float bls[128];

    const int tid = threadIdx.x;
    const int lane = tid & 31, warp = tid >> 5;
    const int wm = warp & 3, wn = warp >> 2;
    const int g = lane >> 2, tg = lane & 3;
    const int m0 = blockIdx.y * 128, n0 = blockIdx.x * 128;

    if (tid < 128) bls[tid] = bl[n0 + tid];

    const int e0 = tid, e1 = tid + 256;
    const int arw0 = e0 >> 2, acq0 = e0 & 3;
    const int arw1 = e1 >> 2, acq1 = e1 & 3;
    const int bk0 = e0 >> 5, bnq0 = e0 & 31;
    const int bk1 = e1 >> 5, bnq1 = e1 & 31;

    float4 ax0, ax1, bx0, bx1;
    ax0 = *(const float4*)(X + (size_t)(m0 + arw0) * INSZ + acq0 * 4);
    ax1 = *(const float4*)(X + (size_t)(m0 + arw1) * INSZ + acq1 * 4);
    bx0 = *(const float4*)(Wih + (size_t)bk0 * G4 + n0 + bnq0 * 4);
    bx1 = *(const float4*)(Wih + (size_t)bk1 * G4 + n0 + bnq1 * 4);
    {
        uint4 u;
        u.x = tf32cvt(ax0.x); u.y = tf32cvt(ax0.y); u.z = tf32cvt(ax0.z); u.w = tf32cvt(ax0.w);
        *(uint4*)&As[0][arw0][acq0 * 4] = u;
        u.x = tf32cvt(ax1.x); u.y = tf32cvt(ax1.y); u.z = tf32cvt(ax1.z); u.w = tf32cvt(ax1.w);
        *(uint4*)&As[0][arw1][acq1 * 4] = u;
        u.x = tf32cvt(bx0.x); u.y = tf32cvt(bx0.y); u.z = tf32cvt(bx0.z); u.w = tf32cvt(bx0.w);
        *(uint4*)&Bs[0][bk0][bnq0 * 4] = u;
        u.x = tf32cvt(bx1.x); u.y = tf32cvt(bx1.y); u.z = tf32cvt(bx1.z); u.w = tf32cvt(bx1.w);
        *(uint4*)&Bs[0][bk1][bnq1 * 4] = u;
    }
    __syncthreads();

    float d[2][8][4];
#pragma unroll
    for (int i = 0; i < 2; i++)
#pragma unroll
        for (int j = 0; j < 8; j++)
#pragma unroll
            for (int q = 0; q < 4; q++) d[i][j][q] = 0.0f;

    for (int kt = 0; kt < 25; kt++) {
        const int cur = kt & 1;
        if (kt < 24) {
            const int kb = (kt + 1) * 16;
            ax0 = *(const float4*)(X + (size_t)(m0 + arw0) * INSZ + kb + acq0 * 4);
            ax1 = *(const float4*)(X + (size_t)(m0 + arw1) * INSZ + kb + acq1 * 4);
            bx0 = *(const float4*)(Wih + (size_t)(kb + bk0) * G4 + n0 + bnq0 * 4);
            bx1 = *(const float4*)(Wih + (size_t)(kb + bk1) * G4 + n0 + bnq1 * 4);
        }
#pragma unroll
        for (int ks = 0; ks < 2; ks++) {
            const int kk = ks * 8;
            unsigned af[2][4];
#pragma unroll
            for (int mt = 0; mt < 2; mt++) {
                const int r = wm * 32 + mt * 16 + g;
                af[mt][0] = As[cur][r][kk + tg];
                af[mt][1] = As[cur][r + 8][kk + tg];
                af[mt][2] = As[cur][r][kk + tg + 4];
                af[mt][3] = As[cur][r + 8][kk + tg + 4];
            }
#pragma unroll
            for (int nt = 0; nt < 8; nt++) {
                const int c = wn * 64 + nt * 8 + g;
                unsigned b0 = Bs[cur][kk + tg][c];
                unsigned b1 = Bs[cur][kk + tg + 4][c];
                mma_tf32(d[0][nt][0], d[0][nt][1], d[0][nt][2], d[0][nt][3],
                         af[0][0], af[0][1], af[0][2], af[0][3], b0, b1);
                mma_tf32(d[1][nt][0], d[1][nt][1], d[1][nt][2], d[1][nt][3],
                         af[1][0], af[1][1], af[1][2], af[1][3], b0, b1);
            }
        }
        if (kt < 24) {
            const int nxt = 1 - cur;
            uint4 u;
            u.x = tf32cvt(ax0.x); u.y = tf32cvt(ax0.y); u.z = tf32cvt(ax0.z); u.w = tf32cvt(ax0.w);
            *(uint4*)&As[nxt][arw0][acq0 * 4] = u;
            u.x = tf32cvt(ax1.x); u.y = tf32cvt(ax1.y); u.z = tf32cvt(ax1.z); u.w = tf32cvt(ax1.w);
            *(uint4*)&As[nxt][arw1][acq1 * 4] = u;
            u.x = tf32cvt(bx0.x); u.y = tf32cvt(bx0.y); u.z = tf32cvt(bx0.z); u.w = tf32cvt(bx0.w);
            *(uint4*)&Bs[nxt][bk0][bnq0 * 4] = u;
            u.x = tf32cvt(bx1.x); u.y = tf32cvt(bx1.y); u.z = tf32cvt(bx1.z); u.w = tf32cvt(bx1.w);
            *(uint4*)&Bs[nxt][bk1][bnq1 * 4] = u;
            __syncthreads();
        }
    }

#pragma unroll
    for (int mt = 0; mt < 2; mt++) {
#pragma unroll
        for (int rp = 0; rp < 2; rp++) {
            const int m = m0 + wm * 32 + mt * 16 + g + rp * 8;
            const int bb = m / TSTEPS, t = m % TSTEPS;
            const float* offrow = (t > 0) ? (Wih + (size_t)(400 + tgt[m - 1]) * G4) : (const float*)0;
            float* dst = g_xw + ((size_t)t * BATCH + bb) * G4 + n0;
#pragma unroll
            for (int nt = 0; nt < 8; nt++) {
                const int c = wn * 64 + nt * 8 + tg * 2;
                float v0 = d[mt][nt][rp * 2 + 0] + bls[c];
                float v1 = d[mt][nt][rp * 2 + 1] + bls[c + 1];
                if (offrow) { v0 += offrow[n0 + c]; v1 += offrow[n0 + c + 1]; }
                float2 v = make_float2(v0, v1);
                *(float2*)(dst + c) = v;
            }
        }
    }
}

// ---------- persistent loop kernel: 128 CTAs x 1024 threads ----------
// resident smem: M [2][256*65], wr [2][1024], wu [2][256]; scratch overlay after.
#define P_M    0
#define P_WR   33280
#define P_WU   35328
#define P_SCR  35840
// scratch (phase M layout; phase L As2/Bs2 overlay the start)
#define S_PART 0        // [2][4224]
#define S_K    8448     // [2][256]
#define S_SIM  8960     // [2][1024]
#define S_WW   11008    // [2][1024]
#define S_H    13056    // [2][256]
#define S_RD   13568    // [2][256]
#define S_PR   14080    // [2][512]
#define S_WP   15104    // [2][40]
#define S_EX   15184    // [2][16]
#define S_SOFT 15216    // [2][16]
#define S_LU   15248    // int [2][4]
#define SCR_FLOATS 15256
#define PK_FLOATS (P_SCR + SCR_FLOATS)
#define PK_BYTES (PK_FLOATS * 4)

#define LBAR() asm volatile("bar.sync 3, 256;" ::: "memory")

__global__ void __launch_bounds__(1024, 1) k_loop(
    const float* __restrict__ Wih, const float* __restrict__ Whh,
    const float* __restrict__ Wkp, const float* __restrict__ bkp,
    const float* __restrict__ Wout, const float* __restrict__ bout,
    float* __restrict__ out)
{
    cg::grid_group grid = cg::this_grid();
    extern __shared__ float sm[];
    const int cta = blockIdx.x;
    const int tid = threadIdx.x;
    const int half = tid >> 9, lt = tid & 511;
    const int lane = tid & 31;
    const int widl = lt >> 5;
    const int bM = cta * 2 + half;

    float* sMall  = sm + P_M;
    float* swrA   = sm + P_WR;
    float* swuA   = sm + P_WU;
    float* scr    = sm + P_SCR;
    float* As2    = scr;             // [2][16][34] phase L
    float* Bs2    = scr + 1088;      // [2][16][68] phase L
    float* spart  = scr + S_PART;
    float* skA    = scr + S_K;
    float* ssimA  = scr + S_SIM;
    float* swwA   = scr + S_WW;
    float* shA    = scr + S_H;
    float* srdA   = scr + S_RD;
    float* spRA   = scr + S_PR;
    float* swpA   = scr + S_WP;
    float* sexA   = scr + S_EX;
    float* ssfA   = scr + S_SOFT;
    int*   sluA   = (int*)(scr + S_LU);

    float* sM     = sMall + half * 16640;
    float* swr    = swrA + half * 1024;
    float* swu    = swuA + half * 256;
    float* sk     = skA + half * 256;
    float* ssim   = ssimA + half * 1024;
    float* sww    = swwA + half * 1024;
    float* sh     = shA + half * 256;
    float* sreads = srdA + half * 256;
    float* spR    = spRA + half * 512;
    float* swp    = swpA + half * 40;
    float* sex    = sexA + half * 16;
    float* ssoft  = ssfA + half * 16;
    int*   slu    = sluA + half * 4;

    // ---- init resident state ----
    for (int e = tid; e < 2 * 16384; e += 1024) {
        int bb = e >> 14, idx = e & 16383;
        sMall[bb * 16640 + (idx >> 6) * 65 + (idx & 63)] = 1e-6f;
    }
    for (int e = tid; e < 2048; e += 1024) swrA[e] = 1.0f / 256.0f;
    if (tid < 512) swuA[tid] = 1.0f / 256.0f;
    if (tid < 512) {
        g_r[cta * 512 + tid] = 0.0f;
        g_hA[cta * 512 + tid] = 0.0f;
    }
    float cA = 0.0f, cB = 0.0f;
    grid.sync();

    const float* WihR = Wih + (size_t)405 * G4;

    for (int t = 0; t < TSTEPS; t++) {
        const float* hin  = (t & 1) ? g_hB : g_hA;
        float*       hout = (t & 1) ? g_hA : g_hB;

        // ===== phase L: LSTM (threads 0-255, R8 k2 verbatim with named barriers) =====
        if (tid < 256) {
            const int tx = tid & 15, ty = tid >> 4;
            const int b0 = (cta & 7) * 32, u0 = (cta >> 3) * 16;
            const int arow = tid >> 3, akq = tid & 7;
            const int bk = tid >> 4, bu = tid & 15;

            const int uP = u0 + tx;
            const int bP0 = b0 + ty * 2, bP1 = bP0 + 1;
            const float* xwAp = g_xw + ((size_t)t * BATCH + bP0) * G4;
            const float* xwBp = g_xw + ((size_t)t * BATCH + bP1) * G4;
            float xA0 = xwAp[uP], xA1 = xwAp[256 + uP], xA2 = xwAp[512 + uP], xA3 = xwAp[768 + uP];
            float xB0 = xwBp[uP], xB1 = xwBp[256 + uP], xB2 = xwBp[512 + uP], xB3 = xwBp[768 + uP];

            {
                float2 av = *(const float2*)(g_r + (size_t)(b0 + arow) * 256 + akq * 2);
                As2[(akq * 2) * 34 + arow] = av.x;
                As2[(akq * 2 + 1) * 34 + arow] = av.y;
                const float* wrow = WihR + (size_t)bk * G4 + u0 + bu;
                Bs2[bk * 68 + bu * 4 + 0] = wrow[0];
                Bs2[bk * 68 + bu * 4 + 1] = wrow[256];
                Bs2[bk * 68 + bu * 4 + 2] = wrow[512];
                Bs2[bk * 68 + bu * 4 + 3] = wrow[768];
            }
            LBAR();

            float a00 = 0, a01 = 0, a02 = 0, a03 = 0;
            float a10 = 0, a11 = 0, a12 = 0, a13 = 0;
            for (int kt = 0; kt < 32; kt++) {
                const int cur = kt & 1;
                float2 avn = make_float2(0.f, 0.f);
                float bg0 = 0.f, bg1 = 0.f, bg2 = 0.f, bg3 = 0.f;
                if (kt < 31) {
                    const int kn = kt + 1;
                    const float* src = (kn < 16) ? g_r : hin;
                    avn = *(const float2*)(src + (size_t)(b0 + arow) * 256 + (kn & 15) * 16 + akq * 2);
                    const float* W = (kn < 16) ? WihR : Whh;
                    const float* wrow = W + (size_t)((kn & 15) * 16 + bk) * G4 + u0 + bu;
                    bg0 = wrow[0]; bg1 = wrow[256]; bg2 = wrow[512]; bg3 = wrow[768];
                }
#pragma unroll
                for (int k = 0; k < 16; k++) {
                    float a0 = As2[cur * 544 + k * 34 + ty * 2];
                    float a1 = As2[cur * 544 + k * 34 + ty * 2 + 1];
                    float4 b4 = *(float4*)&Bs2[cur * 1088 + k * 68 + tx * 4];
                    a00 += a0 * b4.x; a01 += a0 * b4.y; a02 += a0 * b4.z; a03 += a0 * b4.w;
                    a10 += a1 * b4.x; a11 += a1 * b4.y; a12 += a1 * b4.z; a13 += a1 * b4.w;
                }
                if (kt < 31) {
                    const int nxt = 1 - cur;
                    As2[nxt * 544 + (akq * 2) * 34 + arow] = avn.x;
                    As2[nxt * 544 + (akq * 2 + 1) * 34 + arow] = avn.y;
                    Bs2[nxt * 1088 + bk * 68 + bu * 4 + 0] = bg0;
                    Bs2[nxt * 1088 + bk * 68 + bu * 4 + 1] = bg1;
                    Bs2[nxt * 1088 + bk * 68 + bu * 4 + 2] = bg2;
                    Bs2[nxt * 1088 + bk * 68 + bu * 4 + 3] = bg3;
                    LBAR();
                }
            }
            {
                float gi = a00 + xA0, gf = a01 + xA1, gg = a02 + xA2, go = a03 + xA3;
                cA = sigf(gf) * cA + sigf(gi) * tanhf(gg);
                hout[bP0 * 256 + uP] = sigf(go) * tanhf(cA);
            }
            {
                float gi = a10 + xB0, gf = a11 + xB1, gg = a12 + xB2, go = a13 + xB3;
                cB = sigf(gf) * cB + sigf(gi) * tanhf(gg);
                hout[bP1 * 256 + uP] = sigf(go) * tanhf(cB);
            }
        }
        grid.sync();

        // ===== phase M: memory module (R14 k4 verbatim; M/wr/wu resident) =====
        if (lt < 256) sh[lt] = hout[bM * 256 + lt];
        __syncthreads();

        // P1: warps 0-15 shared Wkp GEMV (both batches) | warps 30/31 top-4 per half
        {
            const int warp = tid >> 5;
            if (warp < 16) {
                const int kbase = warp * 16;
                float h0[16], h1[16];
#pragma unroll
                for (int kk = 0; kk < 16; kk++) {
                    h0[kk] = shA[kbase + kk];
                    h1[kk] = shA[256 + kbase + kk];
                }
#pragma unroll
                for (int g = 0; g < 9; g++) {
                    int col = g * 32 + lane;
                    if (col < 260) {
                        const float* wp = Wkp + (size_t)kbase * 260 + col;
                        float p0 = 0.0f, p1 = 0.0f;
#pragma unroll
                        for (int kk = 0; kk < 16; kk++) {
                            float wv = wp[(size_t)kk * 260];
                            p0 += h0[kk] * wv;
                            p1 += h1[kk] * wv;
                        }
                        spart[warp * 264 + col] = p0;
                        spart[4224 + warp * 264 + col] = p1;
                    }
                }
            } else if (warp >= 30) {
                const int hh = warp - 30;
                const float* wu = swuA + hh * 256;
                int* sl = sluA + hh * 4;
                float v[8];
#pragma unroll
                for (int j = 0; j < 8; j++) v[j] = wu[j * 32 + lane];
#pragma unroll
                for (int r = 0; r < 4; r++) {
                    float bv = v[0]; int bi = lane;
#pragma unroll
                    for (int j = 1; j < 8; j++) {
                        int idx = j * 32 + lane;
                        if (v[j] < bv) { bv = v[j]; bi = idx; }
                    }
#pragma unroll
                    for (int o = 16; o > 0; o >>= 1) {
                        float ov = __shfl_xor_sync(0xffffffffu, bv, o);
                        int   oi = __shfl_xor_sync(0xffffffffu, bi, o);
                        if (ov < bv || (ov == bv && oi < bi)) { bv = ov; bi = oi; }
                    }
                    if (lane == 0) sl[r] = bi;
#pragma unroll
                    for (int j = 0; j < 8; j++)
                        if (bi == j * 32 + lane) v[j] = 3.0e38f;
                }
            }
        }
        __syncthreads();

        // P2: kp partial sum + activations
        if (lt < 260) {
            float s = bkp[lt];
            const float* sp = spart + half * 4224;
#pragma unroll
            for (int w = 0; w < 16; w++) s += sp[w * 264 + lt];
            if (lt < 256) sk[lt] = tanhf(s);
            else sex[4 + (lt - 256)] = sigf(s);
        }
        __syncthreads();

        // P3: key norms (warps 0-3 per half)
        if (widl < 4) {
            float v0 = sk[widl * 64 + lane], v1 = sk[widl * 64 + lane + 32];
            float s = v0 * v0 + v1 * v1;
#pragma unroll
            for (int o = 16; o > 0; o >>= 1) s += __shfl_xor_sync(0xffffffffu, s, o);
            if (lane == 0) sex[widl] = 1.0f / (sqrtf(s) + EPSF);
        }
        __syncthreads();

        // P4: write weights
        if (lt < 256) {
            float al0 = sex[4], al1 = sex[5], al2 = sex[6], al3 = sex[7];
            float4 w;
            w.x = al0 * swr[lt]       + (1.0f - al0) * ((lt == slu[0]) ? 1.0f : 0.0f);
            w.y = al1 * swr[256 + lt] + (1.0f - al1) * ((lt == slu[1]) ? 1.0f : 0.0f);
            w.z = al2 * swr[512 + lt] + (1.0f - al2) * ((lt == slu[2]) ? 1.0f : 0.0f);
            w.w = al3 * swr[768 + lt] + (1.0f - al3) * ((lt == slu[3]) ? 1.0f : 0.0f);
            *(float4*)&sww[lt * 4] = w;
        }
        __syncthreads();

        // P5: erase + additive write (M resident in smem only)
        {
            const int d = lt & 63, nb = lt >> 6;
            const int lu0 = slu[0];
            const float k0 = sk[d], k1 = sk[64 + d], k2 = sk[128 + d], k3 = sk[192 + d];
#pragma unroll 4
            for (int e = 0; e < 32; e++) {
                int n = e * 8 + nb;
                float4 w = *(float4*)&sww[n * 4];
                float v = (n == lu0) ? 0.0f : sM[n * 65 + d];
                v += w.x * k0 + w.y * k1 + w.z * k2 + w.w * k3;
                sM[n * 65 + d] = v;
            }
        }
        __syncthreads();

        // P6: row norms + cosine sims (2 threads per row)
        {
            const int row = lt >> 1, hf = lt & 1;
            const float* mrow = sM + row * 65 + hf * 32;
            const float* kb = sk + hf * 32;
            float s = 0, d0 = 0, d1 = 0, d2 = 0, d3 = 0;
#pragma unroll
            for (int dd = 0; dd < 32; dd += 4) {
                float4 kk0 = *(const float4*)&kb[dd];
                float4 kk1 = *(const float4*)&kb[64 + dd];
                float4 kk2 = *(const float4*)&kb[128 + dd];
                float4 kk3 = *(const float4*)&kb[192 + dd];
                float m0 = mrow[dd], m1 = mrow[dd + 1], m2 = mrow[dd + 2], m3 = mrow[dd + 3];
                s  += m0 * m0 + m1 * m1 + m2 * m2 + m3 * m3;
                d0 += m0 * kk0.x + m1 * kk0.y + m2 * kk0.z + m3 * kk0.w;
                d1 += m0 * kk1.x + m1 * kk1.y + m2 * kk1.z + m3 * kk1.w;
                d2 += m0 * kk2.x + m1 * kk2.y + m2 * kk2.z + m3 * kk2.w;
                d3 += m0 * kk3.x + m1 * kk3.y + m2 * kk3.z + m3 * kk3.w;
            }
            s  += __shfl_xor_sync(0xffffffffu, s, 1);
            d0 += __shfl_xor_sync(0xffffffffu, d0, 1);
            d1 += __shfl_xor_sync(0xffffffffu, d1, 1);
            d2 += __shfl_xor_sync(0xffffffffu, d2, 1);
            d3 += __shfl_xor_sync(0xffffffffu, d3, 1);
            if (hf == 0) {
                float inv = 1.0f / (sqrtf(s) + EPSF);
                ssim[row]       = d0 * inv * sex[0];
                ssim[256 + row] = d1 * inv * sex[1];
                ssim[512 + row] = d2 * inv * sex[2];
                ssim[768 + row] = d3 * inv * sex[3];
            }
        }
        __syncthreads();

        // P7: softmax per head
        float e0, e1, e2, e3;
        float* srow = 0;
        int gH = 0;
        if (lt < 256) {
            gH = lt >> 6;
            const int j = lt & 63;
            srow = ssim + gH * 256 + j;
            float v0 = srow[0], v1 = srow[64], v2 = srow[128], v3 = srow[192];
            float mx = fmaxf(fmaxf(v0, v1), fmaxf(v2, v3));
#pragma unroll
            for (int o = 16; o > 0; o >>= 1) mx = fmaxf(mx, __shfl_xor_sync(0xffffffffu, mx, o));
            if (lane == 0) ssoft[gH * 2 + ((lt >> 5) & 1)] = mx;
            e0 = v0; e1 = v1; e2 = v2; e3 = v3;
        }
        __syncthreads();
        if (lt < 256) {
            float mx = fmaxf(ssoft[gH * 2], ssoft[gH * 2 + 1]);
            e0 = expf(e0 - mx); e1 = expf(e1 - mx); e2 = expf(e2 - mx); e3 = expf(e3 - mx);
            float sum = e0 + e1 + e2 + e3;
#pragma unroll
            for (int o = 16; o > 0; o >>= 1) sum += __shfl_xor_sync(0xffffffffu, sum, o);
            if (lane == 0) ssoft[8 + gH * 2 + ((lt >> 5) & 1)] = sum;
        }
        __syncthreads();
        if (lt < 256) {
            float inv = 1.0f / (ssoft[8 + gH * 2] + ssoft[8 + gH * 2 + 1]);
            e0 *= inv; e1 *= inv; e2 *= inv; e3 *= inv;
            srow[0] = e0; srow[64] = e1; srow[128] = e2; srow[192] = e3;
            float wrs = e0 + e1 + e2 + e3;
            float4 w = *(float4*)&sww[lt * 4];
            swu[lt] = GAMMA * swu[lt] + wrs + (w.x + w.y + w.z + w.w);
        }
        __syncthreads();
        if (lt < 256) {
            swr[lt] = ssim[lt]; swr[256 + lt] = ssim[256 + lt];
            swr[512 + lt] = ssim[512 + lt]; swr[768 + lt] = ssim[768 + lt];
        }

        // P8: reads
        {
            const int sub = lt >> 8;
            const int r = (lt >> 6) & 3, dd = lt & 63;
            const float* wr2 = ssim + r * 256 + sub * 128;
            const float* mbase = sM + sub * 128 * 65;
            float acc = 0.0f;
#pragma unroll 4
            for (int n = 0; n < 128; n += 4) {
                float4 w = *(const float4*)&wr2[n];
                acc += w.x * mbase[n * 65 + dd] + w.y * mbase[(n + 1) * 65 + dd]
                     + w.z * mbase[(n + 2) * 65 + dd] + w.w * mbase[(n + 3) * 65 + dd];
            }
            spR[lt] = acc;
        }
        __syncthreads();
        if (lt < 256) {
            float v = spR[lt] + spR[lt + 256];
            sreads[lt] = v;
            g_r[bM * 256 + lt] = v;
        }
        __syncthreads();

        // P9: output head
        if (lt < 256) {
            const float* w1 = Wout + (size_t)lt * 5;
            const float* w2 = Wout + (size_t)(256 + lt) * 5;
            float hv = sh[lt], rv = sreads[lt];
            float p0 = hv * w1[0] + rv * w2[0];
            float p1 = hv * w1[1] + rv * w2[1];
            float p2 = hv * w1[2] + rv * w2[2];
            float p3 = hv * w1[3] + rv * w2[3];
            float p4 = hv * w1[4] + rv * w2[4];
#pragma unroll
            for (int o = 16; o > 0; o >>= 1) {
                p0 += __shfl_xor_sync(0xffffffffu, p0, o);
                p1 += __shfl_xor_sync(0xffffffffu, p1, o);
                p2 += __shfl_xor_sync(0xffffffffu, p2, o);
                p3 += __shfl_xor_sync(0xffffffffu, p3, o);
                p4 += __shfl_xor_sync(0xffffffffu, p4, o);
            }
            if (lane == 0) {
                swp[widl * 5 + 0] = p0; swp[widl * 5 + 1] = p1; swp[widl * 5 + 2] = p2;
                swp[widl * 5 + 3] = p3; swp[widl * 5 + 4] = p4;
            }
        }
        __syncthreads();
        if (lt == 0) {
            float l[5];
#pragma unroll
            for (int c = 0; c < 5; c++) {
                float s = bout[c];
#pragma unroll
                for (int w = 0; w < 8; w++) s += swp[w * 5 + c];
                l[c] = s;
            }
            float mx = l[0];
#pragma unroll
            for (int c = 1; c < 5; c++) mx = fmaxf(mx, l[c]);
            float e[5], s = 0.0f;
#pragma unroll
            for (int c = 0; c < 5; c++) { e[c] = expf(l[c] - mx); s += e[c]; }
            float inv = 1.0f / s;
            float* o = out + ((size_t)bM * TSTEPS + t) * 5;
#pragma unroll
            for (int c = 0; c < 5; c++) o[c] = e[c] * inv;
        }
        grid.sync();
    }
}

// ---------- launch ----------
extern "C" void kernel_launch(void* const* d_in, const int* in_sizes, int n_in,
                              void* d_out, int out_size) {
    const float* X    = (const float*)d_in[0];
    const int*   tgt  = (const int*)d_in[1];
    const float* Wih  = (const float*)d_in[2];
    const float* Whh  = (const float*)d_in[3];
    const float* bl   = (const float*)d_in[4];
    const float* Wkp  = (const float*)d_in[5];
    const float* bkp  = (const float*)d_in[6];
    const float* Wout = (const float*)d_in[7];
    const float* bout = (const float*)d_in[8];
    float* out = (float*)d_out;

    cudaFuncSetAttribute(k_loop, cudaFuncAttributeMaxDynamicSharedMemorySize, PK_BYTES);

    k1_xw_tc<<<dim3(8, 100), 256>>>(X, tgt, Wih, bl);

    void* args[] = { (void*)&Wih, (void*)&Whh, (void*)&Wkp, (void*)&bkp,
                     (void*)&Wout, (void*)&bout, (void*)&out };
    cudaLaunchCooperativeKernel((void*)k_loop, dim3(128), dim3(1024), args,
                                PK_BYTES, (cudaStream_t)0);
}

// round 17
// speedup vs baseline: 1.2587x; 1.1354x over previous
#include <cuda_runtime.h>
#include <cooperative_groups.h>
#include <math.h>

namespace cg = cooperative_groups;

#define BATCH 256
#define TSTEPS 50
#define INSZ 400
#define G4 1024
#define GAMMA 0.95f
#define EPSF 1e-8f

// ---------- device scratch ----------
__device__ float g_xw[TSTEPS * BATCH * G4];
__device__ float g_hA[BATCH * 256];
__device__ float g_hB[BATCH * 256];
__device__ float g_r[BATCH * 256];

__device__ __forceinline__ float sigf(float x) { return 1.0f / (1.0f + expf(-x)); }

__device__ __forceinline__ unsigned tf32cvt(float f) {
    unsigned u;
    asm("cvt.rna.tf32.f32 %0, %1;" : "=r"(u) : "f"(f));
    return u;
}
__device__ __forceinline__ void mma_tf32(
    float& d0, float& d1, float& d2, float& d3,
    unsigned a0, unsigned a1, unsigned a2, unsigned a3,
    unsigned b0, unsigned b1)
{
    asm("mma.sync.aligned.m16n8k8.row.col.f32.tf32.tf32.f32 "
        "{%0,%1,%2,%3}, {%4,%5,%6,%7}, {%8,%9}, {%0,%1,%2,%3};"
        : "+f"(d0), "+f"(d1), "+f"(d2), "+f"(d3)
        : "r"(a0), "r"(a1), "r"(a2), "r"(a3), "r"(b0), "r"(b1));
}

// ---------- K1: tf32 tensor-core GEMM (R13 version, unchanged) ----------
__global__ __launch_bounds__(256) void k1_xw_tc(
    const float* __restrict__ X, const int* __restrict__ tgt,
    const float* __restrict__ Wih, const float* __restrict__ bl)
{
    __shared__ unsigned As[2][128][20];
    __shared__ unsigned Bs[2][16][136];
    __shared__ float bls[128];

    const int tid = threadIdx.x;
    const int lane = tid & 31, warp = tid >> 5;
    const int wm = warp & 3, wn = warp >> 2;
    const int g = lane >> 2, tg = lane & 3;
    const int m0 = blockIdx.y * 128, n0 = blockIdx.x * 128;

    if (tid < 128) bls[tid] = bl[n0 + tid];

    const int e0 = tid, e1 = tid + 256;
    const int arw0 = e0 >> 2, acq0 = e0 & 3;
    const int arw1 = e1 >> 2, acq1 = e1 & 3;
    const int bk0 = e0 >> 5, bnq0 = e0 & 31;
    const int bk1 = e1 >> 5, bnq1 = e1 & 31;

    float4 ax0, ax1, bx0, bx1;
    ax0 = *(const float4*)(X + (size_t)(m0 + arw0) * INSZ + acq0 * 4);
    ax1 = *(const float4*)(X + (size_t)(m0 + arw1) * INSZ + acq1 * 4);
    bx0 = *(const float4*)(Wih + (size_t)bk0 * G4 + n0 + bnq0 * 4);
    bx1 = *(const float4*)(Wih + (size_t)bk1 * G4 + n0 + bnq1 * 4);
    {
        uint4 u;
        u.x = tf32cvt(ax0.x); u.y = tf32cvt(ax0.y); u.z = tf32cvt(ax0.z); u.w = tf32cvt(ax0.w);
        *(uint4*)&As[0][arw0][acq0 * 4] = u;
        u.x = tf32cvt(ax1.x); u.y = tf32cvt(ax1.y); u.z = tf32cvt(ax1.z); u.w = tf32cvt(ax1.w);
        *(uint4*)&As[0][arw1][acq1 * 4] = u;
        u.x = tf32cvt(bx0.x); u.y = tf32cvt(bx0.y); u.z = tf32cvt(bx0.z); u.w = tf32cvt(bx0.w);
        *(uint4*)&Bs[0][bk0][bnq0 * 4] = u;
        u.x = tf32cvt(bx1.x); u.y = tf32cvt(bx1.y); u.z = tf32cvt(bx1.z); u.w = tf32cvt(bx1.w);
        *(uint4*)&Bs[0][bk1][bnq1 * 4] = u;
    }
    __syncthreads();

    float d[2][8][4];
#pragma unroll
    for (int i = 0; i < 2; i++)
#pragma unroll
        for (int j = 0; j < 8; j++)
#pragma unroll
            for (int q = 0; q < 4; q++) d[i][j][q] = 0.0f;

    for (int kt = 0; kt < 25; kt++) {
        const int cur = kt & 1;
        if (kt < 24) {
            const int kb = (kt + 1) * 16;
            ax0 = *(const float4*)(X + (size_t)(m0 + arw0) * INSZ + kb + acq0 * 4);
            ax1 = *(const float4*)(X + (size_t)(m0 + arw1) * INSZ + kb + acq1 * 4);
            bx0 = *(const float4*)(Wih + (size_t)(kb + bk0) * G4 + n0 + bnq0 * 4);
            bx1 = *(const float4*)(Wih + (size_t)(kb + bk1) * G4 + n0 + bnq1 * 4);
        }
#pragma unroll
        for (int ks = 0; ks < 2; ks++) {
            const int kk = ks * 8;
            unsigned af[2][4];
#pragma unroll
            for (int mt = 0; mt < 2; mt++) {
                const int r = wm * 32 + mt * 16 + g;
                af[mt][0] = As[cur][r][kk + tg];
                af[mt][1] = As[cur][r + 8][kk + tg];
                af[mt][2] = As[cur][r][kk + tg + 4];
                af[mt][3] = As[cur][r + 8][kk + tg + 4];
            }
#pragma unroll
            for (int nt = 0; nt < 8; nt++) {
                const int c = wn * 64 + nt * 8 + g;
                unsigned b0 = Bs[cur][kk + tg][c];
                unsigned b1 = Bs[cur][kk + tg + 4][c];
                mma_tf32(d[0][nt][0], d[0][nt][1], d[0][nt][2], d[0][nt][3],
                         af[0][0], af[0][1], af[0][2], af[0][3], b0, b1);
                mma_tf32(d[1][nt][0], d[1][nt][1], d[1][nt][2], d[1][nt][3],
                         af[1][0], af[1][1], af[1][2], af[1][3], b0, b1);
            }
        }
        if (kt < 24) {
            const int nxt = 1 - cur;
            uint4 u;
            u.x = tf32cvt(ax0.x); u.y = tf32cvt(ax0.y); u.z = tf32cvt(ax0.z); u.w = tf32cvt(ax0.w);
            *(uint4*)&As[nxt][arw0][acq0 * 4] = u;
            u.x = tf32cvt(ax1.x); u.y = tf32cvt(ax1.y); u.z = tf32cvt(ax1.z); u.w = tf32cvt(ax1.w);
            *(uint4*)&As[nxt][arw1][acq1 * 4] = u;
            u.x = tf32cvt(bx0.x); u.y = tf32cvt(bx0.y); u.z = tf32cvt(bx0.z); u.w = tf32cvt(bx0.w);
            *(uint4*)&Bs[nxt][bk0][bnq0 * 4] = u;
            u.x = tf32cvt(bx1.x); u.y = tf32cvt(bx1.y); u.z = tf32cvt(bx1.z); u.w = tf32cvt(bx1.w);
            *(uint4*)&Bs[nxt][bk1][bnq1 * 4] = u;
            __syncthreads();
        }
    }

#pragma unroll
    for (int mt = 0; mt < 2; mt++) {
#pragma unroll
        for (int rp = 0; rp < 2; rp++) {
            const int m = m0 + wm * 32 + mt * 16 + g + rp * 8;
            const int bb = m / TSTEPS, t = m % TSTEPS;
            const float* offrow = (t > 0) ? (Wih + (size_t)(400 + tgt[m - 1]) * G4) : (const float*)0;
            float* dst = g_xw + ((size_t)t * BATCH + bb) * G4 + n0;
#pragma unroll
            for (int nt = 0; nt < 8; nt++) {
                const int c = wn * 64 + nt * 8 + tg * 2;
                float v0 = d[mt][nt][rp * 2 + 0] + bls[c];
                float v1 = d[mt][nt][rp * 2 + 1] + bls[c + 1];
                if (offrow) { v0 += offrow[n0 + c]; v1 += offrow[n0 + c + 1]; }
                float2 v = make_float2(v0, v1);
                *(float2*)(dst + c) = v;
            }
        }
    }
}

// ---------- persistent loop kernel: 128 CTAs x 1024 threads ----------
#define P_M    0
#define P_WR   33280
#define P_WU   35328
#define P_SCR  35840
// scratch overlay (phase M layout)
#define S_PART 0        // [2][4224]
#define S_K    8448     // [2][256]
#define S_SIM  8960     // [2][1024]
#define S_WW   11008    // [2][1024]
#define S_H    13056    // [2][256]
#define S_RD   13568    // [2][256]
#define S_PR   14080    // [2][512]
#define S_WP   15104    // [2][40]
#define S_EX   15184    // [2][16]
#define S_SOFT 15216    // [2][16]
#define S_LU   15248    // int [2][4]
#define SCR_FLOATS 15256
#define PK_FLOATS (P_SCR + SCR_FLOATS)
#define PK_BYTES (PK_FLOATS * 4)

#define LBAR() asm volatile("bar.sync 3, 256;" ::: "memory")

__global__ void __launch_bounds__(1024, 1) k_loop(
    const float* __restrict__ Wih, const float* __restrict__ Whh,
    const float* __restrict__ Wkp, const float* __restrict__ bkp,
    const float* __restrict__ Wout, const float* __restrict__ bout,
    float* __restrict__ out)
{
    cg::grid_group grid = cg::this_grid();
    extern __shared__ float sm[];
    const int cta = blockIdx.x;
    const int tid = threadIdx.x;
    const int half = tid >> 9, lt = tid & 511;
    const int lane = tid & 31;
    const int widl = lt >> 5;
    const int bM = cta * 2 + half;

    float* sMall  = sm + P_M;
    float* swrA   = sm + P_WR;
    float* swuA   = sm + P_WU;
    float* scr    = sm + P_SCR;
    // phase-L overlay (inside scratch):
    unsigned* As3 = (unsigned*)scr;            // [2][32][20] = 1280
    unsigned* Bs3 = (unsigned*)(scr + 1280);   // [2][16][72] = 2304
    float*    sg  = scr + 3584;                // [32][68]    = 2176
    // phase-M overlay:
    float* spart  = scr + S_PART;
    float* skA    = scr + S_K;
    float* ssimA  = scr + S_SIM;
    float* swwA   = scr + S_WW;
    float* shA    = scr + S_H;
    float* srdA   = scr + S_RD;
    float* spRA   = scr + S_PR;
    float* swpA   = scr + S_WP;
    float* sexA   = scr + S_EX;
    float* ssfA   = scr + S_SOFT;
    int*   sluA   = (int*)(scr + S_LU);

    float* sM     = sMall + half * 16640;
    float* swr    = swrA + half * 1024;
    float* swu    = swuA + half * 256;
    float* sk     = skA + half * 256;
    float* ssim   = ssimA + half * 1024;
    float* sww    = swwA + half * 1024;
    float* sh     = shA + half * 256;
    float* sreads = srdA + half * 256;
    float* spR    = spRA + half * 512;
    float* swp    = swpA + half * 40;
    float* sex    = sexA + half * 16;
    float* ssoft  = ssfA + half * 16;
    int*   slu    = sluA + half * 4;

    // ---- init resident state ----
    for (int e = tid; e < 2 * 16384; e += 1024) {
        int bb = e >> 14, idx = e & 16383;
        sMall[bb * 16640 + (idx >> 6) * 65 + (idx & 63)] = 1e-6f;
    }
    for (int e = tid; e < 2048; e += 1024) swrA[e] = 1.0f / 256.0f;
    if (tid < 512) swuA[tid] = 1.0f / 256.0f;
    if (tid < 512) {
        g_r[cta * 512 + tid] = 0.0f;
        g_hA[cta * 512 + tid] = 0.0f;
    }
    float cA = 0.0f, cB = 0.0f;
    grid.sync();

    const float* WihR = Wih + (size_t)405 * G4;

    for (int t = 0; t < TSTEPS; t++) {
        const float* hin  = (t & 1) ? g_hB : g_hA;
        float*       hout = (t & 1) ? g_hA : g_hB;

        // ===== phase L: LSTM gates via tf32 mma (threads 0-255, 8 warps) =====
        if (tid < 256) {
            const int tx = tid & 15, ty = tid >> 4;
            const int b0 = (cta & 7) * 32, u0 = (cta >> 3) * 16;
            const int warp = tid >> 5;
            const int gq = (tid & 31) >> 2, tg = tid & 3;   // quad row / quad lane
            const int cbase = warp * 8;
            // staging mapping
            const int am = tid >> 3, ak2 = (tid & 7) * 2;   // As: row, k-pair
            const int bk = tid >> 4, bu = tid & 15;         // Bs

            const int uP = u0 + tx;
            const int bP0 = b0 + ty * 2, bP1 = bP0 + 1;
            const float* xwAp = g_xw + ((size_t)t * BATCH + bP0) * G4;
            const float* xwBp = g_xw + ((size_t)t * BATCH + bP1) * G4;
            float xA0 = xwAp[uP], xA1 = xwAp[256 + uP], xA2 = xwAp[512 + uP], xA3 = xwAp[768 + uP];
            float xB0 = xwBp[uP], xB1 = xwBp[256 + uP], xB2 = xwBp[512 + uP], xB3 = xwBp[768 + uP];

            // preload stage 0
            {
                float2 av = *(const float2*)(g_r + (size_t)(b0 + am) * 256 + ak2);
                As3[am * 20 + ak2]     = tf32cvt(av.x);
                As3[am * 20 + ak2 + 1] = tf32cvt(av.y);
                const float* wrow = WihR + (size_t)bk * G4 + u0 + bu;
                Bs3[bk * 72 + bu * 4 + 0] = tf32cvt(wrow[0]);
                Bs3[bk * 72 + bu * 4 + 1] = tf32cvt(wrow[256]);
                Bs3[bk * 72 + bu * 4 + 2] = tf32cvt(wrow[512]);
                Bs3[bk * 72 + bu * 4 + 3] = tf32cvt(wrow[768]);
            }
            LBAR();

            float d[2][4];
#pragma unroll
            for (int i = 0; i < 2; i++)
#pragma unroll
                for (int q = 0; q < 4; q++) d[i][q] = 0.0f;

            for (int kt = 0; kt < 32; kt++) {
                const int cur = kt & 1;
                float2 avn = make_float2(0.f, 0.f);
                float bg0 = 0.f, bg1 = 0.f, bg2 = 0.f, bg3 = 0.f;
                if (kt < 31) {
                    const int kn = kt + 1;
                    const float* src = (kn < 16) ? g_r : hin;
                    avn = *(const float2*)(src + (size_t)(b0 + am) * 256 + (kn & 15) * 16 + ak2);
                    const float* W = (kn < 16) ? WihR : Whh;
                    const float* wrow = W + (size_t)((kn & 15) * 16 + bk) * G4 + u0 + bu;
                    bg0 = wrow[0]; bg1 = wrow[256]; bg2 = wrow[512]; bg3 = wrow[768];
                }
#pragma unroll
                for (int ks = 0; ks < 2; ks++) {
                    const int kk = ks * 8;
                    unsigned a00 = As3[cur * 640 + gq * 20 + kk + tg];
                    unsigned a01 = As3[cur * 640 + (gq + 8) * 20 + kk + tg];
                    unsigned a02 = As3[cur * 640 + gq * 20 + kk + tg + 4];
                    unsigned a03 = As3[cur * 640 + (gq + 8) * 20 + kk + tg + 4];
                    unsigned a10 = As3[cur * 640 + (16 + gq) * 20 + kk + tg];
                    unsigned a11 = As3[cur * 640 + (24 + gq) * 20 + kk + tg];
                    unsigned a12 = As3[cur * 640 + (16 + gq) * 20 + kk + tg + 4];
                    unsigned a13 = As3[cur * 640 + (24 + gq) * 20 + kk + tg + 4];
                    unsigned b0 = Bs3[cur * 1152 + (kk + tg) * 72 + cbase + gq];
                    unsigned b1 = Bs3[cur * 1152 + (kk + tg + 4) * 72 + cbase + gq];
                    mma_tf32(d[0][0], d[0][1], d[0][2], d[0][3], a00, a01, a02, a03, b0, b1);
                    mma_tf32(d[1][0], d[1][1], d[1][2], d[1][3], a10, a11, a12, a13, b0, b1);
                }
                if (kt < 31) {
                    const int nxt = 1 - cur;
                    As3[nxt * 640 + am * 20 + ak2]     = tf32cvt(avn.x);
                    As3[nxt * 640 + am * 20 + ak2 + 1] = tf32cvt(avn.y);
                    Bs3[nxt * 1152 + bk * 72 + bu * 4 + 0] = tf32cvt(bg0);
                    Bs3[nxt * 1152 + bk * 72 + bu * 4 + 1] = tf32cvt(bg1);
                    Bs3[nxt * 1152 + bk * 72 + bu * 4 + 2] = tf32cvt(bg2);
                    Bs3[nxt * 1152 + bk * 72 + bu * 4 + 3] = tf32cvt(bg3);
                    LBAR();
                }
            }
            // write gates to smem buffer [32 rows][68]
#pragma unroll
            for (int mt = 0; mt < 2; mt++) {
#pragma unroll
                for (int rp = 0; rp < 2; rp++) {
                    const int r = mt * 16 + gq + rp * 8;
                    const int c = cbase + tg * 2;
                    sg[r * 68 + c]     = d[mt][rp * 2 + 0];
                    sg[r * 68 + c + 1] = d[mt][rp * 2 + 1];
                }
            }
            LBAR();
            // LSTM cell (old (b,u) thread ownership; cA/cB persistent)
            {
                float4 gA = *(float4*)&sg[(ty * 2) * 68 + tx * 4];
                float gi = gA.x + xA0, gf = gA.y + xA1, gg2 = gA.z + xA2, go = gA.w + xA3;
                cA = sigf(gf) * cA + sigf(gi) * tanhf(gg2);
                hout[bP0 * 256 + uP] = sigf(go) * tanhf(cA);
            }
            {
                float4 gB = *(float4*)&sg[(ty * 2 + 1) * 68 + tx * 4];
                float gi = gB.x + xB0, gf = gB.y + xB1, gg2 = gB.z + xB2, go = gB.w + xB3;
                cB = sigf(gf) * cB + sigf(gi) * tanhf(gg2);
                hout[bP1 * 256 + uP] = sigf(go) * tanhf(cB);
            }
        }
        grid.sync();

        // ===== phase M: memory module (R16 verbatim) =====
        if (lt < 256) sh[lt] = hout[bM * 256 + lt];
        __syncthreads();

        // P1: warps 0-15 shared Wkp GEMV | warps 30/31 top-4
        {
            const int warp = tid >> 5;
            if (warp < 16) {
                const int kbase = warp * 16;
                float h0[16], h1[16];
#pragma unroll
                for (int kk = 0; kk < 16; kk++) {
                    h0[kk] = shA[kbase + kk];
                    h1[kk] = shA[256 + kbase + kk];
                }
#pragma unroll
                for (int g = 0; g < 9; g++) {
                    int col = g * 32 + lane;
                    if (col < 260) {
                        const float* wp = Wkp + (size_t)kbase * 260 + col;
                        float p0 = 0.0f, p1 = 0.0f;
#pragma unroll
                        for (int kk = 0; kk < 16; kk++) {
                            float wv = wp[(size_t)kk * 260];
                            p0 += h0[kk] * wv;
                            p1 += h1[kk] * wv;
                        }
                        spart[warp * 264 + col] = p0;
                        spart[4224 + warp * 264 + col] = p1;
                    }
                }
            } else if (warp >= 30) {
                const int hh = warp - 30;
                const float* wu = swuA + hh * 256;
                int* sl = sluA + hh * 4;
                float v[8];
#pragma unroll
                for (int j = 0; j < 8; j++) v[j] = wu[j * 32 + lane];
#pragma unroll
                for (int r = 0; r < 4; r++) {
                    float bv = v[0]; int bi = lane;
#pragma unroll
                    for (int j = 1; j < 8; j++) {
                        int idx = j * 32 + lane;
                        if (v[j] < bv) { bv = v[j]; bi = idx; }
                    }
#pragma unroll
                    for (int o = 16; o > 0; o >>= 1) {
                        float ov = __shfl_xor_sync(0xffffffffu, bv, o);
                        int   oi = __shfl_xor_sync(0xffffffffu, bi, o);
                        if (ov < bv || (ov == bv && oi < bi)) { bv = ov; bi = oi; }
                    }
                    if (lane == 0) sl[r] = bi;
#pragma unroll
                    for (int j = 0; j < 8; j++)
                        if (bi == j * 32 + lane) v[j] = 3.0e38f;
                }
            }
        }
        __syncthreads();

        // P2: kp partial sum + activations
        if (lt < 260) {
            float s = bkp[lt];
            const float* sp = spart + half * 4224;
#pragma unroll
            for (int w = 0; w < 16; w++) s += sp[w * 264 + lt];
            if (lt < 256) sk[lt] = tanhf(s);
            else sex[4 + (lt - 256)] = sigf(s);
        }
        __syncthreads();

        // P3: key norms
        if (widl < 4) {
            float v0 = sk[widl * 64 + lane], v1 = sk[widl * 64 + lane + 32];
            float s = v0 * v0 + v1 * v1;
#pragma unroll
            for (int o = 16; o > 0; o >>= 1) s += __shfl_xor_sync(0xffffffffu, s, o);
            if (lane == 0) sex[widl] = 1.0f / (sqrtf(s) + EPSF);
        }
        __syncthreads();

        // P4: write weights
        if (lt < 256) {
            float al0 = sex[4], al1 = sex[5], al2 = sex[6], al3 = sex[7];
            float4 w;
            w.x = al0 * swr[lt]       + (1.0f - al0) * ((lt == slu[0]) ? 1.0f : 0.0f);
            w.y = al1 * swr[256 + lt] + (1.0f - al1) * ((lt == slu[1]) ? 1.0f : 0.0f);
            w.z = al2 * swr[512 + lt] + (1.0f - al2) * ((lt == slu[2]) ? 1.0f : 0.0f);
            w.w = al3 * swr[768 + lt] + (1.0f - al3) * ((lt == slu[3]) ? 1.0f : 0.0f);
            *(float4*)&sww[lt * 4] = w;
        }
        __syncthreads();

        // P5: erase + additive write (M resident)
        {
            const int d2 = lt & 63, nb = lt >> 6;
            const int lu0 = slu[0];
            const float k0 = sk[d2], k1 = sk[64 + d2], k2 = sk[128 + d2], k3 = sk[192 + d2];
#pragma unroll 4
            for (int e = 0; e < 32; e++) {
                int n = e * 8 + nb;
                float4 w = *(float4*)&sww[n * 4];
                float v = (n == lu0) ? 0.0f : sM[n * 65 + d2];
                v += w.x * k0 + w.y * k1 + w.z * k2 + w.w * k3;
                sM[n * 65 + d2] = v;
            }
        }
        __syncthreads();

        // P6: row norms + cosine sims
        {
            const int row = lt >> 1, hf = lt & 1;
            const float* mrow = sM + row * 65 + hf * 32;
            const float* kb = sk + hf * 32;
            float s = 0, d0 = 0, d1 = 0, d2 = 0, d3 = 0;
#pragma unroll
            for (int dd = 0; dd < 32; dd += 4) {
                float4 kk0 = *(const float4*)&kb[dd];
                float4 kk1 = *(const float4*)&kb[64 + dd];
                float4 kk2 = *(const float4*)&kb[128 + dd];
                float4 kk3 = *(const float4*)&kb[192 + dd];
                float m0 = mrow[dd], m1 = mrow[dd + 1], m2 = mrow[dd + 2], m3 = mrow[dd + 3];
                s  += m0 * m0 + m1 * m1 + m2 * m2 + m3 * m3;
                d0 += m0 * kk0.x + m1 * kk0.y + m2 * kk0.z + m3 * kk0.w;
                d1 += m0 * kk1.x + m1 * kk1.y + m2 * kk1.z + m3 * kk1.w;
                d2 += m0 * kk2.x + m1 * kk2.y + m2 * kk2.z + m3 * kk2.w;
                d3 += m0 * kk3.x + m1 * kk3.y + m2 * kk3.z + m3 * kk3.w;
            }
            s  += __shfl_xor_sync(0xffffffffu, s, 1);
            d0 += __shfl_xor_sync(0xffffffffu, d0, 1);
            d1 += __shfl_xor_sync(0xffffffffu, d1, 1);
            d2 += __shfl_xor_sync(0xffffffffu, d2, 1);
            d3 += __shfl_xor_sync(0xffffffffu, d3, 1);
            if (hf == 0) {
                float inv = 1.0f / (sqrtf(s) + EPSF);
                ssim[row]       = d0 * inv * sex[0];
                ssim[256 + row] = d1 * inv * sex[1];
                ssim[512 + row] = d2 * inv * sex[2];
                ssim[768 + row] = d3 * inv * sex[3];
            }
        }
        __syncthreads();

        // P7: softmax per head
        float e0, e1, e2, e3;
        float* srow = 0;
        int gH = 0;
        if (lt < 256) {
            gH = lt >> 6;
            const int j = lt & 63;
            srow = ssim + gH * 256 + j;
            float v0 = srow[0], v1 = srow[64], v2 = srow[128], v3 = srow[192];
            float mx = fmaxf(fmaxf(v0, v1), fmaxf(v2, v3));
#pragma unroll
            for (int o = 16; o > 0; o >>= 1) mx = fmaxf(mx, __shfl_xor_sync(0xffffffffu, mx, o));
            if (lane == 0) ssoft[gH * 2 + ((lt >> 5) & 1)] = mx;
            e0 = v0; e1 = v1; e2 = v2; e3 = v3;
        }
        __syncthreads();
        if (lt < 256) {
            float mx = fmaxf(ssoft[gH * 2], ssoft[gH * 2 + 1]);
            e0 = expf(e0 - mx); e1 = expf(e1 - mx); e2 = expf(e2 - mx); e3 = expf(e3 - mx);
            float sum = e0 + e1 + e2 + e3;
#pragma unroll
            for (int o = 16; o > 0; o >>= 1) sum += __shfl_xor_sync(0xffffffffu, sum, o);
            if (lane == 0) ssoft[8 + gH * 2 + ((lt >> 5) & 1)] = sum;
        }
        __syncthreads();
        if (lt < 256) {
            float inv = 1.0f / (ssoft[8 + gH * 2] + ssoft[8 + gH * 2 + 1]);
            e0 *= inv; e1 *= inv; e2 *= inv; e3 *= inv;
            srow[0] = e0; srow[64] = e1; srow[128] = e2; srow[192] = e3;
            float wrs = e0 + e1 + e2 + e3;
            float4 w = *(float4*)&sww[lt * 4];
            swu[lt] = GAMMA * swu[lt] + wrs + (w.x + w.y + w.z + w.w);
        }
        __syncthreads();
        if (lt < 256) {
            swr[lt] = ssim[lt]; swr[256 + lt] = ssim[256 + lt];
            swr[512 + lt] = ssim[512 + lt]; swr[768 + lt] = ssim[768 + lt];
        }

        // P8: reads
        {
            const int sub = lt >> 8;
            const int r = (lt >> 6) & 3, dd = lt & 63;
            const float* wr2 = ssim + r * 256 + sub * 128;
            const float* mbase = sM + sub * 128 * 65;
            float acc = 0.0f;
#pragma unroll 4
            for (int n = 0; n < 128; n += 4) {
                float4 w = *(const float4*)&wr2[n];
                acc += w.x * mbase[n * 65 + dd] + w.y * mbase[(n + 1) * 65 + dd]
                     + w.z * mbase[(n + 2) * 65 + dd] + w.w * mbase[(n + 3) * 65 + dd];
            }
            spR[lt] = acc;
        }
        __syncthreads();
        if (lt < 256) {
            float v = spR[lt] + spR[lt + 256];
            sreads[lt] = v;
            g_r[bM * 256 + lt] = v;
        }
        __syncthreads();

        // P9: output head
        if (lt < 256) {
            const float* w1 = Wout + (size_t)lt * 5;
            const float* w2 = Wout + (size_t)(256 + lt) * 5;
            float hv = sh[lt], rv = sreads[lt];
            float p0 = hv * w1[0] + rv * w2[0];
            float p1 = hv * w1[1] + rv * w2[1];
            float p2 = hv * w1[2] + rv * w2[2];
            float p3 = hv * w1[3] + rv * w2[3];
            float p4 = hv * w1[4] + rv * w2[4];
#pragma unroll
            for (int o = 16; o > 0; o >>= 1) {
                p0 += __shfl_xor_sync(0xffffffffu, p0, o);
                p1 += __shfl_xor_sync(0xffffffffu, p1, o);
                p2 += __shfl_xor_sync(0xffffffffu, p2, o);
                p3 += __shfl_xor_sync(0xffffffffu, p3, o);
                p4 += __shfl_xor_sync(0xffffffffu, p4, o);
            }
            if (lane == 0) {
                swp[widl * 5 + 0] = p0; swp[widl * 5 + 1] = p1; swp[widl * 5 + 2] = p2;
                swp[widl * 5 + 3] = p3; swp[widl * 5 + 4] = p4;
            }
        }
        __syncthreads();
        if (lt == 0) {
            float l[5];
#pragma unroll
            for (int c = 0; c < 5; c++) {
                float s = bout[c];
#pragma unroll
                for (int w = 0; w < 8; w++) s += swp[w * 5 + c];
                l[c] = s;
            }
            float mx = l[0];
#pragma unroll
            for (int c = 1; c < 5; c++) mx = fmaxf(mx, l[c]);
            float e[5], s = 0.0f;
#pragma unroll
            for (int c = 0; c < 5; c++) { e[c] = expf(l[c] - mx); s += e[c]; }
            float inv = 1.0f / s;
            float* o = out + ((size_t)bM * TSTEPS + t) * 5;
#pragma unroll
            for (int c = 0; c < 5; c++) o[c] = e[c] * inv;
        }
        grid.sync();
    }
}

// ---------- launch ----------
extern "C" void kernel_launch(void* const* d_in, const int* in_sizes, int n_in,
                              void* d_out, int out_size) {
    const float* X    = (const float*)d_in[0];
    const int*   tgt  = (const int*)d_in[1];
    const float* Wih  = (const float*)d_in[2];
    const float* Whh  = (const float*)d_in[3];
    const float* bl   = (const float*)d_in[4];
    const float* Wkp  = (const float*)d_in[5];
    const float* bkp  = (const float*)d_in[6];
    const float* Wout = (const float*)d_in[7];
    const float* bout = (const float*)d_in[8];
    float* out = (float*)d_out;

    cudaFuncSetAttribute(k_loop, cudaFuncAttributeMaxDynamicSharedMemorySize, PK_BYTES);

    k1_xw_tc<<<dim3(8, 100), 256>>>(X, tgt, Wih, bl);

    void* args[] = { (void*)&Wih, (void*)&Whh, (void*)&Wkp, (void*)&bkp,
                     (void*)&Wout, (void*)&bout, (void*)&out };
    cudaLaunchCooperativeKernel((void*)k_loop, dim3(128), dim3(1024), args,
                                PK_BYTES, (cudaStream_t)0);
}